// round 14
// baseline (speedup 1.0000x reference)
#include <cuda_runtime.h>
#include <math.h>

// P2V: out[b,vox] = top2-margin of softmax_n( |s2| * exp(-|s1| * |xyz[b,:,n]-grid[:,vox]|^2) )
// margin = (exp(v0)-exp(v1)) / sum_n exp(v_n),  v_n in (0,1]
//
// v_n = 2^( kx0*g0 + kx1*g1 + kx2*g2 + p_n + lw_vox )   (one MUFU ex2 per n)
//   per-(b,n) table g_tab2[b][pair] = {kx0 pair, kx1 pair, kx2 pair, p pair} (32B rows)
//   lw = log2|s2| - s1*log2e*|g|^2
// R14: per-voxel packed constants {G0,G1,G2,LW} live in SHARED MEMORY (broadcast
// LDS.128 per v-iteration) instead of 32 registers -> true 64-reg state ->
// launch_bounds(128,8) = 32 warps/SM without spilling.
// Sum of exp(v): deg-4 minimax poly (Horner, 4 fma2 incl. fused accumulation, literal coeffs).
// Top-2 tracked on the exponent acc (monotone) via scalar FMNMX (ALU pipe).
// Block epilogue: partials -> padded smem, ONE warp serially reduces the 32 outputs.

typedef unsigned long long u64;

#define VOXN 32768
#define NN   1024

// packed {f,f} bit patterns for deg-4 minimax coeffs of e^x on [0,1] (|err| ~ 3e-5)
#define CQ3 0x3D8E757C3D8E757CULL
#define CQ2 0x3E0F5EAD3E0F5EADULL
#define CQ1 0x3F028A763F028A76ULL
#define CQ0 0x3F7FAD483F7FAD48ULL
#define C0F 1.0000236f

// [b][pair][ kx0_n, kx0_n1, kx1_n, kx1_n1, kx2_n, kx2_n1, p_n, p_n1 ]
__device__ __align__(256) float  g_tab2[4][512][8];
__device__ __align__(16)  float4 g_vox[VOXN];

__device__ __forceinline__ u64 pk2(float lo, float hi) {
    u64 r; asm("mov.b64 %0, {%1, %2};" : "=l"(r) : "f"(lo), "f"(hi)); return r;
}
__device__ __forceinline__ void upk2(u64 v, float& lo, float& hi) {
    asm("mov.b64 {%0, %1}, %2;" : "=f"(lo), "=f"(hi) : "l"(v));
}
__device__ __forceinline__ u64 fma2(u64 a, u64 b, u64 c) {
    u64 d; asm("fma.rn.f32x2 %0, %1, %2, %3;" : "=l"(d) : "l"(a), "l"(b), "l"(c)); return d;
}
__device__ __forceinline__ u64 add2(u64 a, u64 b) {
    u64 d; asm("add.rn.f32x2 %0, %1, %2;" : "=l"(d) : "l"(a), "l"(b)); return d;
}
__device__ __forceinline__ float ex2f(float x) {
    float r; asm("ex2.approx.ftz.f32 %0, %1;" : "=f"(r) : "f"(x)); return r;
}

// ---- fused prologue: blocks 0-127 per-voxel, blocks 128-143 per-(b,n) tables ----
__global__ void pv_prep(const float* __restrict__ xyz,
                        const float* __restrict__ grid,
                        const float* __restrict__ s1,
                        const float* __restrict__ s2) {
    const float L = 1.4426950408889634f;
    float s1a = fabsf(s1[0]);
    if (blockIdx.x < 128) {
        int vx = blockIdx.x * 256 + threadIdx.x;
        float g0 = grid[vx];
        float g1 = grid[VOXN + vx];
        float g2 = grid[2 * VOXN + vx];
        float lw = __log2f(fabsf(s2[0])) - s1a * L * (g0 * g0 + g1 * g1 + g2 * g2);
        g_vox[vx] = make_float4(g0, g1, g2, lw);
    } else {
        int i = (blockIdx.x - 128) * 256 + threadIdx.x;   // 0..4095
        if (i >= 4 * NN) return;
        int b = i >> 10, n = i & (NN - 1);
        float k = 2.0f * s1a * L;
        float x0 = xyz[b * 3 * NN + 0 * NN + n];
        float x1 = xyz[b * 3 * NN + 1 * NN + n];
        float x2 = xyz[b * 3 * NN + 2 * NN + n];
        int pr = n >> 1, h = n & 1;
        g_tab2[b][pr][0 + h] = k * x0;
        g_tab2[b][pr][2 + h] = k * x1;
        g_tab2[b][pr][4 + h] = k * x2;
        g_tab2[b][pr][6 + h] = -s1a * L * (x0 * x0 + x1 * x1 + x2 * x2);
    }
}

// ---- main: one warp -> 4 voxels x 2 batches = 8 outputs; block = 4 warps ----
__global__ void __launch_bounds__(128, 8) pv_main(float* __restrict__ out)
{
    // per-warp per-voxel packed constants: [warp][vox] = { {G0,G1}, {G2,LW} }
    __shared__ __align__(16) ulonglong2 sGL[4][4][2];
    __shared__ float sm0[32][33];
    __shared__ float sm1[32][33];
    __shared__ float sS[32][33];

    int tid  = threadIdx.x;
    int lane = tid & 31;
    int wig  = tid >> 5;                     // 0..3
    int warp = blockIdx.x * 4 + wig;
    int vg   = warp >> 1;                    // voxel group (4 voxels)
    int bh   = warp & 1;                     // batches {2bh, 2bh+1}
    int vox0 = vg * 4;

    // lanes 0-3 of each warp build the packed constant block for their voxel
    if (lane < 4) {
        float4 gv = g_vox[vox0 + lane];
        sGL[wig][lane][0] = make_ulonglong2(pk2(gv.x, gv.x), pk2(gv.y, gv.y));
        sGL[wig][lane][1] = make_ulonglong2(pk2(gv.z, gv.z), pk2(gv.w, gv.w));
    }
    __syncwarp();

    u64 S[8];
    float m0[8], m1[8];
    #pragma unroll
    for (int o = 0; o < 8; o++) { S[o] = 0ull; m0[o] = -1e30f; m1[o] = -1e30f; }

    // table pointer: u64 units. per-b stride = 512 pairs * 4 u64 = 2048.
    const u64* tp = reinterpret_cast<const u64*>(g_tab2) + (u64)(2 * bh) * 2048 + lane * 4;

    #pragma unroll 1
    for (int j = 0; j < 16; j++) {
        ulonglong2 a0 = reinterpret_cast<const ulonglong2*>(tp)[0];        // {kx0, kx1}
        ulonglong2 a1 = reinterpret_cast<const ulonglong2*>(tp)[1];        // {kx2, p}
        ulonglong2 b0 = reinterpret_cast<const ulonglong2*>(tp + 2048)[0];
        ulonglong2 b1 = reinterpret_cast<const ulonglong2*>(tp + 2048)[1];
        u64 X[2][4] = { { a0.x, a0.y, a1.x, a1.y }, { b0.x, b0.y, b1.x, b1.y } };

        #pragma unroll
        for (int v = 0; v < 4; v++) {
            // broadcast LDS.128 x2: {G0,G1}, {G2,LW} for this voxel
            ulonglong2 gl0 = sGL[wig][v][0];
            ulonglong2 gl1 = sGL[wig][v][1];
            #pragma unroll
            for (int bi = 0; bi < 2; bi++) {
                int o = v * 2 + bi;
                u64 acc = fma2(X[bi][0], gl0.x, add2(X[bi][3], gl1.y));
                acc = fma2(X[bi][1], gl0.y, acc);
                acc = fma2(X[bi][2], gl1.x, acc);
                float alo, ahi; upk2(acc, alo, ahi);
                // issue MUFU early...
                u64 vv = pk2(ex2f(alo), ex2f(ahi));      // v in [0,1]
                // ...top-2 on exponent (ALU pipe) fills the MUFU shadow
                m1[o] = fmaxf(m1[o], fminf(m0[o], alo));
                m0[o] = fmaxf(m0[o], alo);
                m1[o] = fmaxf(m1[o], fminf(m0[o], ahi));
                m0[o] = fmaxf(m0[o], ahi);
                // Horner deg-4 with fused accumulation (4 fma2, literal coeffs)
                u64 q = fma2(CQ3, vv, CQ2);
                q = fma2(q, vv, CQ1);
                q = fma2(q, vv, CQ0);
                S[o] = fma2(q, vv, S[o]);
            }
        }
        tp += 128;
    }

    // dump per-lane partials to smem (one row per output, padded stride 33)
    #pragma unroll
    for (int o = 0; o < 8; o++) {
        float slo, shi; upk2(S[o], slo, shi);
        int outid = wig * 8 + o;
        sm0[outid][lane] = m0[o];
        sm1[outid][lane] = m1[o];
        sS[outid][lane]  = slo + shi;
    }
    __syncthreads();

    // one warp reduces all 32 outputs of the block (race-free serial scan)
    if (tid < 32) {
        int t = tid;                         // output id within block
        float M0 = -1e30f, M1 = -1e30f, Sf = 0.f;
        #pragma unroll
        for (int l = 0; l < 32; l++) {
            float a = sm0[t][l];
            float b = sm1[t][l];
            M1 = fmaxf(fmaxf(M1, b), fminf(M0, a));
            M0 = fmaxf(M0, a);
            Sf += sS[t][l];
        }
        float v0 = exp2f(M0), v1 = exp2f(M1);
        float res = (__expf(v0) - __expf(v1)) / (Sf + 1024.0f * C0F);

        int w  = t >> 3;                     // warp in block
        int o  = t & 7;
        int wr = blockIdx.x * 4 + w;
        int vgr = wr >> 1, bhr = wr & 1;
        int v  = o >> 1, bi = o & 1;
        out[(2 * bhr + bi) * VOXN + vgr * 4 + v] = res;
    }
}

extern "C" void kernel_launch(void* const* d_in, const int* in_sizes, int n_in,
                              void* d_out, int out_size) {
    const float* xyz = nullptr; const float* grid = nullptr;
    const float* s1 = nullptr;  const float* s2 = nullptr;
    for (int i = 0; i < n_in; i++) {
        if (in_sizes[i] == 4 * 3 * NN)      xyz = (const float*)d_in[i];
        else if (in_sizes[i] == 3 * VOXN)   grid = (const float*)d_in[i];
        else if (in_sizes[i] == 1) { if (!s1) s1 = (const float*)d_in[i]; else s2 = (const float*)d_in[i]; }
    }
    float* out = (float*)d_out;

    pv_prep<<<144, 256>>>(xyz, grid, s1, s2);
    // 131072 outputs, 8 per warp -> 16384 warps -> 4096 blocks of 4 warps
    pv_main<<<4096, 128>>>(out);
}

// round 15
// speedup vs baseline: 2.3291x; 2.3291x over previous
#include <cuda_runtime.h>
#include <math.h>

// P2V: out[b,vox] = top2-margin of softmax_n( |s2| * exp(-|s1| * |xyz[b,:,n]-grid[:,vox]|^2) )
// margin = (exp(v0)-exp(v1)) / sum_n exp(v_n),  v_n in (0,1]
//
// v_n = 2^( kx0*g0 + kx1*g1 + kx2*g2 + p_n + lw_vox )   (one MUFU ex2 per n)
//   per-(b,n) table g_tab2[b][pair] = {kx0 pair, kx1 pair, kx2 pair, p pair} (32B rows)
//   lw = log2|s2| - s1*log2e*|g|^2  (computed in-warp from grid; no g_vox table)
// Sum of exp(v): deg-4 minimax poly (Horner, 4 fma2 incl. fused accumulation), +1024*c0 once.
// Top-2 tracked on the exponent acc (monotone) via scalar FMNMX (ALU pipe).
// Block epilogue: partials -> padded smem, ONE warp serially reduces the 32 outputs.
// R15 vs the 56.7us best (R12): identical loop; g_vox prologue folded into pv_main
// (prep launch shrinks 144->16 blocks, g_vox global round-trip removed).

typedef unsigned long long u64;

#define VOXN 32768
#define NN   1024

// deg-4 minimax coeffs for e^x on [0,1], |err| ~ 3e-5
#define C4F 0.0695600f
#define C3F 0.1400096f
#define C2F 0.5099252f
#define C1F 0.9987378f
#define C0F 1.0000236f

// [b][pair][ kx0_n, kx0_n1, kx1_n, kx1_n1, kx2_n, kx2_n1, p_n, p_n1 ]
__device__ __align__(256) float g_tab2[4][512][8];

__device__ __forceinline__ u64 pk2(float lo, float hi) {
    u64 r; asm("mov.b64 %0, {%1, %2};" : "=l"(r) : "f"(lo), "f"(hi)); return r;
}
__device__ __forceinline__ void upk2(u64 v, float& lo, float& hi) {
    asm("mov.b64 {%0, %1}, %2;" : "=f"(lo), "=f"(hi) : "l"(v));
}
__device__ __forceinline__ u64 fma2(u64 a, u64 b, u64 c) {
    u64 d; asm("fma.rn.f32x2 %0, %1, %2, %3;" : "=l"(d) : "l"(a), "l"(b), "l"(c)); return d;
}
__device__ __forceinline__ u64 add2(u64 a, u64 b) {
    u64 d; asm("add.rn.f32x2 %0, %1, %2;" : "=l"(d) : "l"(a), "l"(b)); return d;
}
__device__ __forceinline__ float ex2f(float x) {
    float r; asm("ex2.approx.ftz.f32 %0, %1;" : "=f"(r) : "f"(x)); return r;
}

// ---- prologue: per-(b,n) table only (16 blocks) ----
__global__ void pv_prep(const float* __restrict__ xyz, const float* __restrict__ s1) {
    const float L = 1.4426950408889634f;
    int i = blockIdx.x * 256 + threadIdx.x;   // 0..4095
    if (i >= 4 * NN) return;
    float s1a = fabsf(s1[0]);
    int b = i >> 10, n = i & (NN - 1);
    float k = 2.0f * s1a * L;
    float x0 = xyz[b * 3 * NN + 0 * NN + n];
    float x1 = xyz[b * 3 * NN + 1 * NN + n];
    float x2 = xyz[b * 3 * NN + 2 * NN + n];
    int pr = n >> 1, h = n & 1;
    g_tab2[b][pr][0 + h] = k * x0;
    g_tab2[b][pr][2 + h] = k * x1;
    g_tab2[b][pr][4 + h] = k * x2;
    g_tab2[b][pr][6 + h] = -s1a * L * (x0 * x0 + x1 * x1 + x2 * x2);
}

// ---- main: one warp -> 4 voxels x 2 batches = 8 outputs; block = 4 warps ----
__global__ void __launch_bounds__(128, 7) pv_main(const float* __restrict__ grid,
                                                  const float* __restrict__ s1,
                                                  const float* __restrict__ s2,
                                                  float* __restrict__ out)
{
    __shared__ float sm0[32][33];
    __shared__ float sm1[32][33];
    __shared__ float sS[32][33];

    int tid  = threadIdx.x;
    int lane = tid & 31;
    int wig  = tid >> 5;                     // 0..3
    int warp = blockIdx.x * 4 + wig;
    int vg   = warp >> 1;                    // voxel group (4 voxels)
    int bh   = warp & 1;                     // batches {2bh, 2bh+1}
    int vox0 = vg * 4;

    // per-voxel constants computed in-warp from grid (lanes 0-3), broadcast by shfl
    const float L = 1.4426950408889634f;
    float g0r = 0.f, g1r = 0.f, g2r = 0.f, lwr = 0.f;
    if (lane < 4) {
        int vx = vox0 + lane;
        g0r = grid[vx];
        g1r = grid[VOXN + vx];
        g2r = grid[2 * VOXN + vx];
        lwr = __log2f(fabsf(s2[0])) - fabsf(s1[0]) * L * (g0r * g0r + g1r * g1r + g2r * g2r);
    }
    u64 G[4][3], LW[4];
    #pragma unroll
    for (int v = 0; v < 4; v++) {
        float a = __shfl_sync(0xffffffffu, g0r, v);
        float b = __shfl_sync(0xffffffffu, g1r, v);
        float c = __shfl_sync(0xffffffffu, g2r, v);
        float d = __shfl_sync(0xffffffffu, lwr, v);
        G[v][0] = pk2(a, a);
        G[v][1] = pk2(b, b);
        G[v][2] = pk2(c, c);
        LW[v]   = pk2(d, d);
    }

    const u64 Cq3 = pk2(C4F, C4F);
    const u64 Cq2 = pk2(C3F, C3F);
    const u64 Cq1 = pk2(C2F, C2F);
    const u64 Cq0 = pk2(C1F, C1F);

    u64 S[8];
    float m0[8], m1[8];
    #pragma unroll
    for (int o = 0; o < 8; o++) { S[o] = 0ull; m0[o] = -1e30f; m1[o] = -1e30f; }

    // table pointer: u64 units. per-b stride = 512 pairs * 4 u64 = 2048.
    const u64* tp = reinterpret_cast<const u64*>(g_tab2) + (u64)(2 * bh) * 2048 + lane * 4;

    #pragma unroll 2
    for (int j = 0; j < 16; j++) {
        ulonglong2 a0 = reinterpret_cast<const ulonglong2*>(tp)[0];        // {kx0, kx1}
        ulonglong2 a1 = reinterpret_cast<const ulonglong2*>(tp)[1];        // {kx2, p}
        ulonglong2 b0 = reinterpret_cast<const ulonglong2*>(tp + 2048)[0];
        ulonglong2 b1 = reinterpret_cast<const ulonglong2*>(tp + 2048)[1];
        u64 X[2][4] = { { a0.x, a0.y, a1.x, a1.y }, { b0.x, b0.y, b1.x, b1.y } };

        #pragma unroll
        for (int v = 0; v < 4; v++) {
            #pragma unroll
            for (int bi = 0; bi < 2; bi++) {
                int o = v * 2 + bi;
                u64 acc = fma2(X[bi][0], G[v][0], add2(X[bi][3], LW[v]));
                acc = fma2(X[bi][1], G[v][1], acc);
                acc = fma2(X[bi][2], G[v][2], acc);
                float alo, ahi; upk2(acc, alo, ahi);
                // issue MUFU early...
                u64 vv = pk2(ex2f(alo), ex2f(ahi));      // v in [0,1]
                // ...top-2 on exponent (ALU pipe) fills the MUFU shadow
                m1[o] = fmaxf(m1[o], fminf(m0[o], alo));
                m0[o] = fmaxf(m0[o], alo);
                m1[o] = fmaxf(m1[o], fminf(m0[o], ahi));
                m0[o] = fmaxf(m0[o], ahi);
                // Horner deg-4 with fused accumulation (4 fma2 total)
                u64 q = fma2(Cq3, vv, Cq2);
                q = fma2(q, vv, Cq1);
                q = fma2(q, vv, Cq0);
                S[o] = fma2(q, vv, S[o]);
            }
        }
        tp += 128;
    }

    // dump per-lane partials to smem (one row per output, padded stride 33)
    #pragma unroll
    for (int o = 0; o < 8; o++) {
        float slo, shi; upk2(S[o], slo, shi);
        int outid = wig * 8 + o;
        sm0[outid][lane] = m0[o];
        sm1[outid][lane] = m1[o];
        sS[outid][lane]  = slo + shi;
    }
    __syncthreads();

    // one warp reduces all 32 outputs of the block (race-free serial scan)
    if (tid < 32) {
        int t = tid;                         // output id within block
        float M0 = -1e30f, M1 = -1e30f, Sf = 0.f;
        #pragma unroll
        for (int l = 0; l < 32; l++) {
            float a = sm0[t][l];
            float b = sm1[t][l];
            M1 = fmaxf(fmaxf(M1, b), fminf(M0, a));
            M0 = fmaxf(M0, a);
            Sf += sS[t][l];
        }
        float v0 = exp2f(M0), v1 = exp2f(M1);
        float res = (__expf(v0) - __expf(v1)) / (Sf + 1024.0f * C0F);

        int w  = t >> 3;                     // warp in block
        int o  = t & 7;
        int wr = blockIdx.x * 4 + w;
        int vgr = wr >> 1, bhr = wr & 1;
        int v  = o >> 1, bi = o & 1;
        out[(2 * bhr + bi) * VOXN + vgr * 4 + v] = res;
    }
}

extern "C" void kernel_launch(void* const* d_in, const int* in_sizes, int n_in,
                              void* d_out, int out_size) {
    const float* xyz = nullptr; const float* grid = nullptr;
    const float* s1 = nullptr;  const float* s2 = nullptr;
    for (int i = 0; i < n_in; i++) {
        if (in_sizes[i] == 4 * 3 * NN)      xyz = (const float*)d_in[i];
        else if (in_sizes[i] == 3 * VOXN)   grid = (const float*)d_in[i];
        else if (in_sizes[i] == 1) { if (!s1) s1 = (const float*)d_in[i]; else s2 = (const float*)d_in[i]; }
    }
    float* out = (float*)d_out;

    pv_prep<<<16, 256>>>(xyz, s1);
    // 131072 outputs, 8 per warp -> 16384 warps -> 4096 blocks of 4 warps
    pv_main<<<4096, 128>>>(grid, s1, s2, out);
}

// round 16
// speedup vs baseline: 2.3511x; 1.0095x over previous
#include <cuda_runtime.h>
#include <math.h>

// P2V: out[b,vox] = top2-margin of softmax_n( |s2| * exp(-|s1| * |xyz[b,:,n]-grid[:,vox]|^2) )
// margin = (exp(v0)-exp(v1)) / sum_n exp(v_n),  v_n in (0,1]
//
// v_n = 2^( kx0*g0 + kx1*g1 + kx2*g2 + p_n + lw_vox )   (one MUFU ex2 per n)
//   per-(b,n) table g_tab2[b][pair] = {kx0 pair, kx1 pair, kx2 pair, p pair} (32B rows)
//   lw = log2|s2| - s1*log2e*|g|^2  (per-voxel table {g0,g1,g2,lw})
// Sum of exp(v): deg-4 minimax poly (Horner, 4 fma2 incl. fused accumulation), +1024*c0 once.
// Top-2 tracked on the exponent acc (monotone) via scalar FMNMX (ALU pipe).
// Block epilogue: partials -> padded smem, ONE warp serially reduces the 32 outputs.
// R16 vs R12 (56.7us best): unroll 1 (halved load transients) + manual 2-unit
// software pipeline per v (batched ex2, top-2 in MUFU shadow, independent polys).

typedef unsigned long long u64;

#define VOXN 32768
#define NN   1024

// deg-4 minimax coeffs for e^x on [0,1], |err| ~ 3e-5
#define C4F 0.0695600f
#define C3F 0.1400096f
#define C2F 0.5099252f
#define C1F 0.9987378f
#define C0F 1.0000236f

// [b][pair][ kx0_n, kx0_n1, kx1_n, kx1_n1, kx2_n, kx2_n1, p_n, p_n1 ]
__device__ __align__(256) float  g_tab2[4][512][8];
__device__ __align__(16)  float4 g_vox[VOXN];

__device__ __forceinline__ u64 pk2(float lo, float hi) {
    u64 r; asm("mov.b64 %0, {%1, %2};" : "=l"(r) : "f"(lo), "f"(hi)); return r;
}
__device__ __forceinline__ void upk2(u64 v, float& lo, float& hi) {
    asm("mov.b64 {%0, %1}, %2;" : "=f"(lo), "=f"(hi) : "l"(v));
}
__device__ __forceinline__ u64 fma2(u64 a, u64 b, u64 c) {
    u64 d; asm("fma.rn.f32x2 %0, %1, %2, %3;" : "=l"(d) : "l"(a), "l"(b), "l"(c)); return d;
}
__device__ __forceinline__ u64 add2(u64 a, u64 b) {
    u64 d; asm("add.rn.f32x2 %0, %1, %2;" : "=l"(d) : "l"(a), "l"(b)); return d;
}
__device__ __forceinline__ float ex2f(float x) {
    float r; asm("ex2.approx.ftz.f32 %0, %1;" : "=f"(r) : "f"(x)); return r;
}

// ---- fused prologue: blocks 0-127 per-voxel, blocks 128-143 per-(b,n) tables ----
__global__ void pv_prep(const float* __restrict__ xyz,
                        const float* __restrict__ grid,
                        const float* __restrict__ s1,
                        const float* __restrict__ s2) {
    const float L = 1.4426950408889634f;
    float s1a = fabsf(s1[0]);
    if (blockIdx.x < 128) {
        int vx = blockIdx.x * 256 + threadIdx.x;
        float g0 = grid[vx];
        float g1 = grid[VOXN + vx];
        float g2 = grid[2 * VOXN + vx];
        float lw = __log2f(fabsf(s2[0])) - s1a * L * (g0 * g0 + g1 * g1 + g2 * g2);
        g_vox[vx] = make_float4(g0, g1, g2, lw);
    } else {
        int i = (blockIdx.x - 128) * 256 + threadIdx.x;   // 0..4095
        if (i >= 4 * NN) return;
        int b = i >> 10, n = i & (NN - 1);
        float k = 2.0f * s1a * L;
        float x0 = xyz[b * 3 * NN + 0 * NN + n];
        float x1 = xyz[b * 3 * NN + 1 * NN + n];
        float x2 = xyz[b * 3 * NN + 2 * NN + n];
        int pr = n >> 1, h = n & 1;
        g_tab2[b][pr][0 + h] = k * x0;
        g_tab2[b][pr][2 + h] = k * x1;
        g_tab2[b][pr][4 + h] = k * x2;
        g_tab2[b][pr][6 + h] = -s1a * L * (x0 * x0 + x1 * x1 + x2 * x2);
    }
}

// ---- main: one warp -> 4 voxels x 2 batches = 8 outputs; block = 4 warps ----
__global__ void __launch_bounds__(128, 7) pv_main(float* __restrict__ out)
{
    __shared__ float sm0[32][33];
    __shared__ float sm1[32][33];
    __shared__ float sS[32][33];

    int tid  = threadIdx.x;
    int lane = tid & 31;
    int wig  = tid >> 5;                     // 0..3
    int warp = blockIdx.x * 4 + wig;
    int vg   = warp >> 1;                    // voxel group (4 voxels)
    int bh   = warp & 1;                     // batches {2bh, 2bh+1}
    int vox0 = vg * 4;

    // per-voxel broadcast constants
    u64 G[4][3], LW[4];
    #pragma unroll
    for (int v = 0; v < 4; v++) {
        float4 gv = g_vox[vox0 + v];
        G[v][0] = pk2(gv.x, gv.x);
        G[v][1] = pk2(gv.y, gv.y);
        G[v][2] = pk2(gv.z, gv.z);
        LW[v]   = pk2(gv.w, gv.w);
    }

    const u64 Cq3 = pk2(C4F, C4F);
    const u64 Cq2 = pk2(C3F, C3F);
    const u64 Cq1 = pk2(C2F, C2F);
    const u64 Cq0 = pk2(C1F, C1F);

    u64 S[8];
    float m0[8], m1[8];
    #pragma unroll
    for (int o = 0; o < 8; o++) { S[o] = 0ull; m0[o] = -1e30f; m1[o] = -1e30f; }

    // table pointer: u64 units. per-b stride = 512 pairs * 4 u64 = 2048.
    const u64* tp = reinterpret_cast<const u64*>(g_tab2) + (u64)(2 * bh) * 2048 + lane * 4;

    #pragma unroll 1
    for (int j = 0; j < 16; j++) {
        ulonglong2 a0 = reinterpret_cast<const ulonglong2*>(tp)[0];        // {kx0, kx1}
        ulonglong2 a1 = reinterpret_cast<const ulonglong2*>(tp)[1];        // {kx2, p}
        ulonglong2 b0 = reinterpret_cast<const ulonglong2*>(tp + 2048)[0];
        ulonglong2 b1 = reinterpret_cast<const ulonglong2*>(tp + 2048)[1];

        #pragma unroll
        for (int v = 0; v < 4; v++) {
            int oA = v * 2, oB = v * 2 + 1;
            // --- phase 1: both units' exponents (8 independent fma-class ops) ---
            u64 accA = fma2(a0.x, G[v][0], add2(a1.y, LW[v]));
            u64 accB = fma2(b0.x, G[v][0], add2(b1.y, LW[v]));
            accA = fma2(a0.y, G[v][1], accA);
            accB = fma2(b0.y, G[v][1], accB);
            accA = fma2(a1.x, G[v][2], accA);
            accB = fma2(b1.x, G[v][2], accB);
            float A0, A1, B0, B1;
            upk2(accA, A0, A1);
            upk2(accB, B0, B1);
            // --- phase 2: batch all 4 MUFU issues ---
            float eA0 = ex2f(A0);
            float eA1 = ex2f(A1);
            float eB0 = ex2f(B0);
            float eB1 = ex2f(B1);
            // --- phase 3: top-2 on exponents (ALU pipe) fills the MUFU shadow ---
            m1[oA] = fmaxf(m1[oA], fminf(m0[oA], A0));
            m0[oA] = fmaxf(m0[oA], A0);
            m1[oA] = fmaxf(m1[oA], fminf(m0[oA], A1));
            m0[oA] = fmaxf(m0[oA], A1);
            m1[oB] = fmaxf(m1[oB], fminf(m0[oB], B0));
            m0[oB] = fmaxf(m0[oB], B0);
            m1[oB] = fmaxf(m1[oB], fminf(m0[oB], B1));
            m0[oB] = fmaxf(m0[oB], B1);
            // --- phase 4: two independent Horner chains (4 fma2 each) ---
            u64 vvA = pk2(eA0, eA1);
            u64 vvB = pk2(eB0, eB1);
            u64 qA = fma2(Cq3, vvA, Cq2);
            u64 qB = fma2(Cq3, vvB, Cq2);
            qA = fma2(qA, vvA, Cq1);
            qB = fma2(qB, vvB, Cq1);
            qA = fma2(qA, vvA, Cq0);
            qB = fma2(qB, vvB, Cq0);
            S[oA] = fma2(qA, vvA, S[oA]);
            S[oB] = fma2(qB, vvB, S[oB]);
        }
        tp += 128;
    }

    // dump per-lane partials to smem (one row per output, padded stride 33)
    #pragma unroll
    for (int o = 0; o < 8; o++) {
        float slo, shi; upk2(S[o], slo, shi);
        int outid = wig * 8 + o;
        sm0[outid][lane] = m0[o];
        sm1[outid][lane] = m1[o];
        sS[outid][lane]  = slo + shi;
    }
    __syncthreads();

    // one warp reduces all 32 outputs of the block (race-free serial scan)
    if (tid < 32) {
        int t = tid;                         // output id within block
        float M0 = -1e30f, M1 = -1e30f, Sf = 0.f;
        #pragma unroll
        for (int l = 0; l < 32; l++) {
            float a = sm0[t][l];
            float b = sm1[t][l];
            M1 = fmaxf(fmaxf(M1, b), fminf(M0, a));
            M0 = fmaxf(M0, a);
            Sf += sS[t][l];
        }
        float v0 = exp2f(M0), v1 = exp2f(M1);
        float res = (__expf(v0) - __expf(v1)) / (Sf + 1024.0f * C0F);

        int w  = t >> 3;                     // warp in block
        int o  = t & 7;
        int wr = blockIdx.x * 4 + w;
        int vgr = wr >> 1, bhr = wr & 1;
        int v  = o >> 1, bi = o & 1;
        out[(2 * bhr + bi) * VOXN + vgr * 4 + v] = res;
    }
}

extern "C" void kernel_launch(void* const* d_in, const int* in_sizes, int n_in,
                              void* d_out, int out_size) {
    const float* xyz = nullptr; const float* grid = nullptr;
    const float* s1 = nullptr;  const float* s2 = nullptr;
    for (int i = 0; i < n_in; i++) {
        if (in_sizes[i] == 4 * 3 * NN)      xyz = (const float*)d_in[i];
        else if (in_sizes[i] == 3 * VOXN)   grid = (const float*)d_in[i];
        else if (in_sizes[i] == 1) { if (!s1) s1 = (const float*)d_in[i]; else s2 = (const float*)d_in[i]; }
    }
    float* out = (float*)d_out;

    pv_prep<<<144, 256>>>(xyz, grid, s1, s2);
    // 131072 outputs, 8 per warp -> 16384 warps -> 4096 blocks of 4 warps
    pv_main<<<4096, 128>>>(out);
}